// round 1
// baseline (speedup 1.0000x reference)
#include <cuda_runtime.h>

#define KDIM 512
#define NDIM 256
#define BM 128
#define BN 128
#define BK 16

// Scratch: in-degree mask (N = 50000 <= 65536). __device__ global per alloc rules.
__device__ unsigned char g_mask[65536];

__global__ void k_zero_mask(int n) {
    int i = blockIdx.x * blockDim.x + threadIdx.x;
    if (i < n) g_mask[i] = 0;
}

__global__ void k_scatter_mask(const int* __restrict__ dst, int e) {
    int i = blockIdx.x * blockDim.x + threadIdx.x;
    if (i < e) g_mask[dst[i]] = 1;
}

// C[M,256] = mask[m] * (A[M,512] @ B[512,256])
// 128x128x16 tiles, 256 threads, 8x8 microtile, f32x2 packed FMA inner loop,
// smem double buffered with register prefetch.
__global__ __launch_bounds__(256, 2)
void k_sgemm_mask(const float* __restrict__ A, const float* __restrict__ B,
                  float* __restrict__ C, int M)
{
    __shared__ float As[2][BK][BM];
    __shared__ float Bs[2][BK][BN];

    const int tid  = threadIdx.x;
    const int row0 = blockIdx.y * BM;
    const int col0 = blockIdx.x * BN;

    // A tile loaders: 128 rows x 16 k; each thread: 2 x float4 along K
    const int aRow = tid >> 2;         // 0..63 (+64 second half)
    const int aCol = (tid & 3) << 2;   // 0,4,8,12
    // B tile loaders: 16 k x 128 cols; each thread: 2 x float4 along N
    const int bRow = tid >> 5;         // 0..7 (+8 second half)
    const int bCol = (tid & 31) << 2;  // 0..124

    const int ty = tid >> 4;           // 0..15 -> 8 output rows each
    const int tx = tid & 15;           // 0..15 -> 8 output cols each

    unsigned long long acc[8][4];
#pragma unroll
    for (int i = 0; i < 8; i++)
#pragma unroll
        for (int p = 0; p < 4; p++) acc[i][p] = 0ull;

    float4 aReg0, aReg1, bReg0, bReg1;

    // ---- prologue: load tile 0 ----
    {
        int grow0 = row0 + aRow;
        int grow1 = row0 + aRow + 64;
        aReg0 = (grow0 < M) ? *(const float4*)(A + (size_t)grow0 * KDIM + aCol)
                            : make_float4(0.f, 0.f, 0.f, 0.f);
        aReg1 = (grow1 < M) ? *(const float4*)(A + (size_t)grow1 * KDIM + aCol)
                            : make_float4(0.f, 0.f, 0.f, 0.f);
        bReg0 = *(const float4*)(B + (size_t)(bRow)     * NDIM + col0 + bCol);
        bReg1 = *(const float4*)(B + (size_t)(bRow + 8) * NDIM + col0 + bCol);
    }
    {
        int r0 = aRow, r1 = aRow + 64;
        As[0][aCol + 0][r0] = aReg0.x; As[0][aCol + 1][r0] = aReg0.y;
        As[0][aCol + 2][r0] = aReg0.z; As[0][aCol + 3][r0] = aReg0.w;
        As[0][aCol + 0][r1] = aReg1.x; As[0][aCol + 1][r1] = aReg1.y;
        As[0][aCol + 2][r1] = aReg1.z; As[0][aCol + 3][r1] = aReg1.w;
        *(float4*)&Bs[0][bRow][bCol]     = bReg0;
        *(float4*)&Bs[0][bRow + 8][bCol] = bReg1;
    }
    __syncthreads();

    const int NT = KDIM / BK;  // 32
    for (int t = 0; t < NT; t++) {
        const int cur = t & 1;

        if (t + 1 < NT) {
            int k0 = (t + 1) * BK;
            int grow0 = row0 + aRow;
            int grow1 = row0 + aRow + 64;
            aReg0 = (grow0 < M) ? *(const float4*)(A + (size_t)grow0 * KDIM + k0 + aCol)
                                : make_float4(0.f, 0.f, 0.f, 0.f);
            aReg1 = (grow1 < M) ? *(const float4*)(A + (size_t)grow1 * KDIM + k0 + aCol)
                                : make_float4(0.f, 0.f, 0.f, 0.f);
            bReg0 = *(const float4*)(B + (size_t)(k0 + bRow)     * NDIM + col0 + bCol);
            bReg1 = *(const float4*)(B + (size_t)(k0 + bRow + 8) * NDIM + col0 + bCol);
        }

#pragma unroll
        for (int k = 0; k < BK; k++) {
            float a[8];
            *(float4*)(a)     = *(const float4*)&As[cur][k][ty * 8];
            *(float4*)(a + 4) = *(const float4*)&As[cur][k][ty * 8 + 4];
            unsigned long long bp[4];
            *(ulonglong2*)(bp)     = *(const ulonglong2*)&Bs[cur][k][tx * 8];
            *(ulonglong2*)(bp + 2) = *(const ulonglong2*)&Bs[cur][k][tx * 8 + 4];

            unsigned long long ad[8];
#pragma unroll
            for (int i = 0; i < 8; i++)
                asm("mov.b64 %0, {%1, %1};" : "=l"(ad[i]) : "r"(__float_as_uint(a[i])));

#pragma unroll
            for (int i = 0; i < 8; i++)
#pragma unroll
                for (int p = 0; p < 4; p++)
                    asm("fma.rn.f32x2 %0, %1, %2, %3;"
                        : "=l"(acc[i][p])
                        : "l"(ad[i]), "l"(bp[p]), "l"(acc[i][p]));
        }

        if (t + 1 < NT) {
            const int nxt = cur ^ 1;
            int r0 = aRow, r1 = aRow + 64;
            As[nxt][aCol + 0][r0] = aReg0.x; As[nxt][aCol + 1][r0] = aReg0.y;
            As[nxt][aCol + 2][r0] = aReg0.z; As[nxt][aCol + 3][r0] = aReg0.w;
            As[nxt][aCol + 0][r1] = aReg1.x; As[nxt][aCol + 1][r1] = aReg1.y;
            As[nxt][aCol + 2][r1] = aReg1.z; As[nxt][aCol + 3][r1] = aReg1.w;
            *(float4*)&Bs[nxt][bRow][bCol]     = bReg0;
            *(float4*)&Bs[nxt][bRow + 8][bCol] = bReg1;
            __syncthreads();
        }
    }

    // ---- epilogue: apply in-degree mask, store ----
#pragma unroll
    for (int i = 0; i < 8; i++) {
        int r = row0 + ty * 8 + i;
        if (r < M) {
            float m = (float)g_mask[r];
            float o[8];
#pragma unroll
            for (int p = 0; p < 4; p++) {
                float2 f = *(float2*)&acc[i][p];
                o[2 * p]     = f.x * m;
                o[2 * p + 1] = f.y * m;
            }
            float* cp = C + (size_t)r * NDIM + col0 + tx * 8;
            *(float4*)cp       = *(float4*)(o);
            *(float4*)(cp + 4) = *(float4*)(o + 4);
        }
    }
}

extern "C" void kernel_launch(void* const* d_in, const int* in_sizes, int n_in,
                              void* d_out, int out_size) {
    const float* x  = (const float*)d_in[0];   // [N, 512]
    const int*   ei = (const int*)d_in[1];     // [2, E] int32
    const float* W  = (const float*)d_in[3];   // [512, 256]
    float* out = (float*)d_out;                // [N, 256]

    const int E = in_sizes[1] / 2;
    const int M = in_sizes[0] / KDIM;          // N nodes
    const int* dst = ei + E;                   // edge_index[1]

    k_zero_mask<<<(M + 255) / 256, 256>>>(M);
    k_scatter_mask<<<(E + 255) / 256, 256>>>(dst, E);

    dim3 grid(NDIM / BN, (M + BM - 1) / BM);
    k_sgemm_mask<<<grid, 256>>>(x, W, out, M);
}

// round 3
// speedup vs baseline: 1.7592x; 1.7592x over previous
#include <cuda_runtime.h>
#include <cuda_bf16.h>
#include <cstdint>

#define KDIM 512
#define NDIM 256
#define BM 128
#define BN 128
#define KC 32
#define NSTAGE (KDIM / KC)   // 16

// Stage smem layout (bytes): A_hi 8K | A_lo 8K | B_hi 8K | B_lo 8K = 32K, x2 buffers
#define ST_AHI 0
#define ST_ALO 8192
#define ST_BHI 16384
#define ST_BLO 24576
#define STAGE_SZ 32768
#define SMEM_TOTAL (2 * STAGE_SZ)   // 65536

__device__ unsigned char g_mask[65536];
__device__ __nv_bfloat16 g_Wt_hi[NDIM * KDIM];   // [n][k] = bf16_hi(W[k][n])
__device__ __nv_bfloat16 g_Wt_lo[NDIM * KDIM];   // residual

// ---------------- helpers ----------------
__device__ __forceinline__ uint32_t smem_u32(const void* p) {
    uint32_t a;
    asm("{ .reg .u64 t; cvta.to.shared.u64 t, %1; cvt.u32.u64 %0, t; }" : "=r"(a) : "l"(p));
    return a;
}
// rows of 64B (4 x 16B chunks); chunk permuted by row for conflict-free ldmatrix
__device__ __forceinline__ uint32_t swz(uint32_t row, uint32_t chunk) {
    return row * 64u + ((chunk ^ ((row & 6u) >> 1)) << 4);
}
__device__ __forceinline__ void ldm4(uint32_t* r, uint32_t addr) {
    asm volatile("ldmatrix.sync.aligned.m8n8.x4.shared.b16 {%0,%1,%2,%3}, [%4];"
                 : "=r"(r[0]), "=r"(r[1]), "=r"(r[2]), "=r"(r[3]) : "r"(addr));
}
__device__ __forceinline__ void mma16816(float* d, const uint32_t* a, uint32_t b0, uint32_t b1) {
    asm volatile("mma.sync.aligned.m16n8k16.row.col.f32.bf16.bf16.f32 "
                 "{%0,%1,%2,%3}, {%4,%5,%6,%7}, {%8,%9}, {%0,%1,%2,%3};"
                 : "+f"(d[0]), "+f"(d[1]), "+f"(d[2]), "+f"(d[3])
                 : "r"(a[0]), "r"(a[1]), "r"(a[2]), "r"(a[3]), "r"(b0), "r"(b1));
}
__device__ __forceinline__ void cpa16(uint32_t dst, const void* src) {
    asm volatile("cp.async.cg.shared.global [%0], [%1], 16;" :: "r"(dst), "l"(src));
}
__device__ __forceinline__ uint32_t pack_bf2(float a, float b) {
    __nv_bfloat162 t = __floats2bfloat162_rn(a, b);
    return *(uint32_t*)&t;
}

// ---------------- prep kernels ----------------
__global__ void k_zero_mask(int n) {
    int i = blockIdx.x * blockDim.x + threadIdx.x;
    if (i < n) g_mask[i] = 0;
}
__global__ void k_scatter_mask(const int* __restrict__ dst, int e) {
    int i = blockIdx.x * blockDim.x + threadIdx.x;
    if (i < e) g_mask[dst[i]] = 1;
}
__global__ void k_prep_w(const float* __restrict__ W) {
    int i = blockIdx.x * blockDim.x + threadIdx.x;
    if (i < NDIM * KDIM) {
        int k = i >> 8;
        int n = i & 255;
        float v = W[i];                       // W[k][n]
        __nv_bfloat16 h = __float2bfloat16(v);
        float l = v - __bfloat162float(h);
        g_Wt_hi[(size_t)n * KDIM + k] = h;
        g_Wt_lo[(size_t)n * KDIM + k] = __float2bfloat16(l);
    }
}

// ---------------- GEMM: C = mask * (A @ W), bf16 3-term split, HMMA ----------------
__global__ __launch_bounds__(256, 1)
void k_gemm(const float* __restrict__ A, float* __restrict__ C, int M)
{
    extern __shared__ char smem[];
    const uint32_t sbase = smem_u32(smem);
    const int tid  = threadIdx.x;
    const int lane = tid & 31;
    const int wid  = tid >> 5;
    const int warp_m = wid >> 2;   // 0..1  -> 64 rows
    const int warp_n = wid & 3;    // 0..3  -> 32 cols
    const int row0 = blockIdx.x * BM;
    const int n0   = blockIdx.y * BN;

    // Loader mapping: thread -> (row lr, half lh)
    const int lr = tid >> 1;       // 0..127
    const int lh = tid & 1;        // 16-float half of the 32-float chunk row
    const bool arow_ok = (row0 + lr) < M;
    const float* aptr = A + (size_t)(row0 + lr) * KDIM + lh * 16;
    const __nv_bfloat16* bh_ptr = g_Wt_hi + (size_t)(n0 + lr) * KDIM + lh * 16;
    const __nv_bfloat16* bl_ptr = g_Wt_lo + (size_t)(n0 + lr) * KDIM + lh * 16;

    float4 av[4];                  // prefetched A f32 (16 floats)
    float acc[4][4][4];
#pragma unroll
    for (int i = 0; i < 4; i++)
#pragma unroll
        for (int j = 0; j < 4; j++)
#pragma unroll
            for (int q = 0; q < 4; q++) acc[i][j][q] = 0.f;

    // ---- prologue: stage 0 into buffer 0 ----
#pragma unroll
    for (int j = 0; j < 4; j++)
        av[j] = arow_ok ? *(const float4*)(aptr + 4 * j) : make_float4(0.f, 0.f, 0.f, 0.f);
    {
        const uint32_t b0 = sbase;  // buffer 0
#pragma unroll
        for (int j = 0; j < 2; j++) {
            uint32_t c = lh * 2 + j;
            uint32_t d = swz(lr, c);
            cpa16(b0 + ST_BHI + d, bh_ptr + j * 8);
            cpa16(b0 + ST_BLO + d, bl_ptr + j * 8);
        }
#pragma unroll
        for (int j = 0; j < 4; j++) {
            float4 v = av[j];
            __nv_bfloat16 hx = __float2bfloat16(v.x), hy = __float2bfloat16(v.y);
            __nv_bfloat16 hz = __float2bfloat16(v.z), hw = __float2bfloat16(v.w);
            uint2 hi2, lo2;
            hi2.x = (uint32_t(__bfloat16_as_ushort(hy)) << 16) | __bfloat16_as_ushort(hx);
            hi2.y = (uint32_t(__bfloat16_as_ushort(hw)) << 16) | __bfloat16_as_ushort(hz);
            lo2.x = pack_bf2(v.x - __bfloat162float(hx), v.y - __bfloat162float(hy));
            lo2.y = pack_bf2(v.z - __bfloat162float(hz), v.w - __bfloat162float(hw));
            uint32_t chunk = lh * 2 + (j >> 1), sub = (j & 1) * 8;
            uint32_t d = swz(lr, chunk) + sub;
            *(uint2*)(smem + ST_AHI + d) = hi2;
            *(uint2*)(smem + ST_ALO + d) = lo2;
        }
        asm volatile("cp.async.commit_group;" ::: "memory");
        asm volatile("cp.async.wait_group 0;" ::: "memory");
    }
    __syncthreads();

    // fragment base rows (within tile)
    const uint32_t amrow = warp_m * 64 + (lane & 15);
    const uint32_t bnrow = warp_n * 32 + (lane & 15);
    const uint32_t chalf = (lane >> 4);   // 16B chunk half select

    for (int t = 0; t < NSTAGE; t++) {
        const uint32_t buf  = sbase + (uint32_t)(t & 1) * STAGE_SZ;
        const uint32_t nbuf = sbase + (uint32_t)((t + 1) & 1) * STAGE_SZ;

        if (t + 1 < NSTAGE) {
            const int koff = (t + 1) * KC;
#pragma unroll
            for (int j = 0; j < 4; j++)
                av[j] = arow_ok ? *(const float4*)(aptr + koff + 4 * j)
                                : make_float4(0.f, 0.f, 0.f, 0.f);
#pragma unroll
            for (int j = 0; j < 2; j++) {
                uint32_t c = lh * 2 + j;
                uint32_t d = swz(lr, c);
                cpa16(nbuf + ST_BHI + d, bh_ptr + koff + j * 8);
                cpa16(nbuf + ST_BLO + d, bl_ptr + koff + j * 8);
            }
            asm volatile("cp.async.commit_group;" ::: "memory");
        }

        // ---- compute stage t ----
#pragma unroll
        for (int ks = 0; ks < 2; ks++) {
            const uint32_t chunk = ks * 2 + chalf;
            uint32_t ah[4][4], al[4][4], bh[2][4], bl[2][4];
#pragma unroll
            for (int mb = 0; mb < 4; mb++) {
                uint32_t r = amrow + mb * 16;
                uint32_t d = swz(r, chunk);
                ldm4(ah[mb], buf + ST_AHI + d);
                ldm4(al[mb], buf + ST_ALO + d);
            }
#pragma unroll
            for (int nb = 0; nb < 2; nb++) {
                uint32_t r = bnrow + nb * 16;
                uint32_t d = swz(r, chunk);
                ldm4(bh[nb], buf + ST_BHI + d);
                ldm4(bl[nb], buf + ST_BLO + d);
            }
#pragma unroll
            for (int mb = 0; mb < 4; mb++)
#pragma unroll
                for (int nb = 0; nb < 2; nb++) {
                    float* a0 = acc[mb][nb * 2 + 0];
                    float* a1 = acc[mb][nb * 2 + 1];
                    mma16816(a0, ah[mb], bh[nb][0], bh[nb][2]);   // hi*hi
                    mma16816(a0, ah[mb], bl[nb][0], bl[nb][2]);   // hi*lo
                    mma16816(a0, al[mb], bh[nb][0], bh[nb][2]);   // lo*hi
                    mma16816(a1, ah[mb], bh[nb][1], bh[nb][3]);
                    mma16816(a1, ah[mb], bl[nb][1], bl[nb][3]);
                    mma16816(a1, al[mb], bh[nb][1], bh[nb][3]);
                }
        }

        if (t + 1 < NSTAGE) {
            // STS A for next stage (after compute so LDG latency overlaps MMA)
#pragma unroll
            for (int j = 0; j < 4; j++) {
                float4 v = av[j];
                __nv_bfloat16 hx = __float2bfloat16(v.x), hy = __float2bfloat16(v.y);
                __nv_bfloat16 hz = __float2bfloat16(v.z), hw = __float2bfloat16(v.w);
                uint2 hi2, lo2;
                hi2.x = (uint32_t(__bfloat16_as_ushort(hy)) << 16) | __bfloat16_as_ushort(hx);
                hi2.y = (uint32_t(__bfloat16_as_ushort(hw)) << 16) | __bfloat16_as_ushort(hz);
                lo2.x = pack_bf2(v.x - __bfloat162float(hx), v.y - __bfloat162float(hy));
                lo2.y = pack_bf2(v.z - __bfloat162float(hz), v.w - __bfloat162float(hw));
                uint32_t chunk = lh * 2 + (j >> 1), sub = (j & 1) * 8;
                uint32_t d = swz(lr, chunk) + sub;
                *(uint2*)((char*)smem + ((t + 1) & 1) * STAGE_SZ + ST_AHI + d) = hi2;
                *(uint2*)((char*)smem + ((t + 1) & 1) * STAGE_SZ + ST_ALO + d) = lo2;
            }
            asm volatile("cp.async.wait_group 0;" ::: "memory");
            __syncthreads();
        }
    }

    // ---- epilogue: mask + store ----
    const int g  = lane >> 2;
    const int tg = lane & 3;
#pragma unroll
    for (int mb = 0; mb < 4; mb++) {
        int r = row0 + warp_m * 64 + mb * 16 + g;
        float m0 = (r     < M) ? (float)g_mask[r]     : 0.f;
        float m1 = (r + 8 < M) ? (float)g_mask[r + 8] : 0.f;
#pragma unroll
        for (int nb = 0; nb < 4; nb++) {
            int c = n0 + warp_n * 32 + nb * 8 + tg * 2;
            if (r < M) {
                float2 o = make_float2(acc[mb][nb][0] * m0, acc[mb][nb][1] * m0);
                *(float2*)(C + (size_t)r * NDIM + c) = o;
            }
            if (r + 8 < M) {
                float2 o = make_float2(acc[mb][nb][2] * m1, acc[mb][nb][3] * m1);
                *(float2*)(C + (size_t)(r + 8) * NDIM + c) = o;
            }
        }
    }
}

// ---------------- launch ----------------
extern "C" void kernel_launch(void* const* d_in, const int* in_sizes, int n_in,
                              void* d_out, int out_size) {
    const float* x  = (const float*)d_in[0];   // [N, 512]
    const int*   ei = (const int*)d_in[1];     // [2, E] int32
    const float* W  = (const float*)d_in[3];   // [512, 256]
    float* out = (float*)d_out;                // [N, 256]

    const int E = in_sizes[1] / 2;
    const int M = in_sizes[0] / KDIM;
    const int* dst = ei + E;

    cudaFuncSetAttribute(k_gemm, cudaFuncAttributeMaxDynamicSharedMemorySize, SMEM_TOTAL);

    k_prep_w<<<(NDIM * KDIM + 255) / 256, 256>>>(W);
    k_zero_mask<<<(M + 255) / 256, 256>>>(M);
    k_scatter_mask<<<(E + 255) / 256, 256>>>(dst, E);

    dim3 grid((M + BM - 1) / BM, NDIM / BN);
    k_gemm<<<grid, 256, SMEM_TOTAL>>>(x, out, M);
}

// round 4
// speedup vs baseline: 2.4090x; 1.3694x over previous
#include <cuda_runtime.h>
#include <cuda_fp16.h>
#include <cstdint>

#define KDIM 512
#define NDIM 256
#define BM 64
#define BN 128
#define KC 32
#define NSTAGE (KDIM / KC)   // 16

// Stage smem (bytes): A_hi 4K | A_lo 4K | B 8K = 16K, double buffered = 32K
#define ST_AHI 0
#define ST_ALO 4096
#define ST_B   8192
#define STAGE_SZ 16384
#define SMEM_TOTAL (2 * STAGE_SZ)

__device__ unsigned char g_mask[65536];
__device__ __half g_Wh[NDIM * KDIM];   // [n][k] = fp16(W[k][n])

// ---------------- helpers ----------------
__device__ __forceinline__ uint32_t smem_u32(const void* p) {
    uint32_t a;
    asm("{ .reg .u64 t; cvta.to.shared.u64 t, %1; cvt.u32.u64 %0, t; }" : "=r"(a) : "l"(p));
    return a;
}
// rows of 64B (4 x 16B chunks); chunk permuted by row -> conflict-free ldmatrix/STS
__device__ __forceinline__ uint32_t swz(uint32_t row, uint32_t chunk) {
    return row * 64u + ((chunk ^ ((row & 6u) >> 1)) << 4);
}
__device__ __forceinline__ void ldm4(uint32_t* r, uint32_t addr) {
    asm volatile("ldmatrix.sync.aligned.m8n8.x4.shared.b16 {%0,%1,%2,%3}, [%4];"
                 : "=r"(r[0]), "=r"(r[1]), "=r"(r[2]), "=r"(r[3]) : "r"(addr));
}
__device__ __forceinline__ void mma16816(float* d, const uint32_t* a, uint32_t b0, uint32_t b1) {
    asm volatile("mma.sync.aligned.m16n8k16.row.col.f32.f16.f16.f32 "
                 "{%0,%1,%2,%3}, {%4,%5,%6,%7}, {%8,%9}, {%0,%1,%2,%3};"
                 : "+f"(d[0]), "+f"(d[1]), "+f"(d[2]), "+f"(d[3])
                 : "r"(a[0]), "r"(a[1]), "r"(a[2]), "r"(a[3]), "r"(b0), "r"(b1));
}
__device__ __forceinline__ void cpa16(uint32_t dst, const void* src) {
    asm volatile("cp.async.cg.shared.global [%0], [%1], 16;" :: "r"(dst), "l"(src));
}
__device__ __forceinline__ uint32_t pack_h2(__half a, __half b) {
    __half2 t = __halves2half2(a, b);
    return *(uint32_t*)&t;
}

// ---------------- prep kernels ----------------
__global__ void k_zero_mask(int n) {
    int i = blockIdx.x * blockDim.x + threadIdx.x;
    if (i < n) g_mask[i] = 0;
}
__global__ void k_scatter_mask(const int* __restrict__ dst, int e4, int e) {
    int i = blockIdx.x * blockDim.x + threadIdx.x;
    if (i < e4) {
        int4 v = *(const int4*)(dst + 4 * i);
        g_mask[v.x] = 1; g_mask[v.y] = 1; g_mask[v.z] = 1; g_mask[v.w] = 1;
    }
    int r = e4 * 4 + i;
    if (r < e) g_mask[dst[r]] = 1;
}
__global__ void k_prep_w(const float* __restrict__ W) {
    int i = blockIdx.x * blockDim.x + threadIdx.x;
    if (i < NDIM * KDIM) {
        int k = i >> 8;
        int n = i & 255;
        g_Wh[(size_t)n * KDIM + k] = __float2half_rn(W[i]);   // W[k][n]
    }
}

// ---------------- GEMM: C = mask * ((A_hi + A_lo) @ fp16(W)), HMMA ----------------
__global__ __launch_bounds__(256, 2)
void k_gemm(const float* __restrict__ A, float* __restrict__ C, int M)
{
    extern __shared__ char smem[];
    const uint32_t sbase = smem_u32(smem);
    const int tid  = threadIdx.x;
    const int lane = tid & 31;
    const int wid  = tid >> 5;
    const int warp_m = wid >> 2;   // 0..1 -> 32 rows
    const int warp_n = wid & 3;    // 0..3 -> 32 cols
    const int row0 = blockIdx.x * BM;
    const int n0   = blockIdx.y * BN;

    // A loader: 64 rows x 32 f32 -> thread = (row tid>>2, chunk tid&3) 8 floats
    const int arow   = tid >> 2;
    const int achunk = tid & 3;
    const bool arow_ok = (row0 + arow) < M;
    const float* aptr = A + (size_t)(row0 + arow) * KDIM + achunk * 8;
    const uint32_t a_sw = swz((uint32_t)arow, (uint32_t)achunk);
    // B loader: 128 rows x 32 f16 -> thread = (row tid>>1, half tid&1) 16 halves
    const int brow  = tid >> 1;
    const int bhalf = tid & 1;
    const __half* bptr = g_Wh + (size_t)(n0 + brow) * KDIM + bhalf * 16;
    const uint32_t b_sw0 = swz((uint32_t)brow, (uint32_t)(bhalf * 2 + 0));
    const uint32_t b_sw1 = swz((uint32_t)brow, (uint32_t)(bhalf * 2 + 1));

    float acc[2][4][4];
#pragma unroll
    for (int i = 0; i < 2; i++)
#pragma unroll
        for (int j = 0; j < 4; j++)
#pragma unroll
            for (int q = 0; q < 4; q++) acc[i][j][q] = 0.f;

    float4 av[2];

    // Convert 8 floats -> hi/lo fp16 uint4s, store to stage buffer
    auto sts_a = [&](char* buf, const float4& v0, const float4& v1) {
        __half h[8]; float l[8];
        const float* f = &v0.x;
#pragma unroll
        for (int j = 0; j < 4; j++) { h[j] = __float2half_rn(f[j]); l[j] = f[j] - __half2float(h[j]); }
        const float* g2 = &v1.x;
#pragma unroll
        for (int j = 0; j < 4; j++) { h[4 + j] = __float2half_rn(g2[j]); l[4 + j] = g2[j] - __half2float(h[4 + j]); }
        uint4 hi, lo;
        hi.x = pack_h2(h[0], h[1]); hi.y = pack_h2(h[2], h[3]);
        hi.z = pack_h2(h[4], h[5]); hi.w = pack_h2(h[6], h[7]);
        lo.x = pack_h2(__float2half_rn(l[0]), __float2half_rn(l[1]));
        lo.y = pack_h2(__float2half_rn(l[2]), __float2half_rn(l[3]));
        lo.z = pack_h2(__float2half_rn(l[4]), __float2half_rn(l[5]));
        lo.w = pack_h2(__float2half_rn(l[6]), __float2half_rn(l[7]));
        *(uint4*)(buf + ST_AHI + a_sw) = hi;
        *(uint4*)(buf + ST_ALO + a_sw) = lo;
    };

    // ---- prologue: stage 0 -> buffer 0 ----
    av[0] = arow_ok ? *(const float4*)(aptr)     : make_float4(0.f, 0.f, 0.f, 0.f);
    av[1] = arow_ok ? *(const float4*)(aptr + 4) : make_float4(0.f, 0.f, 0.f, 0.f);
    cpa16(sbase + ST_B + b_sw0, bptr);
    cpa16(sbase + ST_B + b_sw1, bptr + 8);
    asm volatile("cp.async.commit_group;" ::: "memory");
    sts_a(smem, av[0], av[1]);
    asm volatile("cp.async.wait_group 0;" ::: "memory");
    __syncthreads();

    const uint32_t amrow = (uint32_t)(warp_m * 32 + (lane & 15));
    const uint32_t bnrow = (uint32_t)(warp_n * 32 + (lane & 15));
    const uint32_t chalf = (uint32_t)(lane >> 4);

    for (int t = 0; t < NSTAGE; t++) {
        const uint32_t buf = sbase + (uint32_t)(t & 1) * STAGE_SZ;

        if (t + 1 < NSTAGE) {
            const int koff = (t + 1) * KC;
            av[0] = arow_ok ? *(const float4*)(aptr + koff)     : make_float4(0.f, 0.f, 0.f, 0.f);
            av[1] = arow_ok ? *(const float4*)(aptr + koff + 4) : make_float4(0.f, 0.f, 0.f, 0.f);
            const uint32_t nbuf = sbase + (uint32_t)((t + 1) & 1) * STAGE_SZ;
            cpa16(nbuf + ST_B + b_sw0, bptr + koff);
            cpa16(nbuf + ST_B + b_sw1, bptr + koff + 8);
            asm volatile("cp.async.commit_group;" ::: "memory");
        }

        // ---- compute stage t: 2 k-steps of 16 ----
#pragma unroll
        for (int ks = 0; ks < 2; ks++) {
            const uint32_t chunk = (uint32_t)ks * 2 + chalf;
            uint32_t ah[2][4], al[2][4], bh[2][4];
#pragma unroll
            for (int mb = 0; mb < 2; mb++) {
                uint32_t d = swz(amrow + mb * 16, chunk);
                ldm4(ah[mb], buf + ST_AHI + d);
                ldm4(al[mb], buf + ST_ALO + d);
            }
#pragma unroll
            for (int nb = 0; nb < 2; nb++) {
                uint32_t d = swz(bnrow + nb * 16, chunk);
                ldm4(bh[nb], buf + ST_B + d);
            }
#pragma unroll
            for (int mb = 0; mb < 2; mb++)
#pragma unroll
                for (int nb = 0; nb < 2; nb++) {
                    mma16816(acc[mb][nb * 2 + 0], ah[mb], bh[nb][0], bh[nb][2]);
                    mma16816(acc[mb][nb * 2 + 0], al[mb], bh[nb][0], bh[nb][2]);
                    mma16816(acc[mb][nb * 2 + 1], ah[mb], bh[nb][1], bh[nb][3]);
                    mma16816(acc[mb][nb * 2 + 1], al[mb], bh[nb][1], bh[nb][3]);
                }
        }

        if (t + 1 < NSTAGE) {
            char* nb = smem + ((t + 1) & 1) * STAGE_SZ;
            sts_a(nb, av[0], av[1]);
            asm volatile("cp.async.wait_group 0;" ::: "memory");
            __syncthreads();
        }
    }

    // ---- epilogue: mask + store ----
    const int g  = lane >> 2;
    const int tg = lane & 3;
#pragma unroll
    for (int mb = 0; mb < 2; mb++) {
        int r = row0 + warp_m * 32 + mb * 16 + g;
        float m0 = (r     < M) ? (float)g_mask[r]     : 0.f;
        float m1 = (r + 8 < M) ? (float)g_mask[r + 8] : 0.f;
#pragma unroll
        for (int nb = 0; nb < 4; nb++) {
            int c = n0 + warp_n * 32 + nb * 8 + tg * 2;
            if (r < M) {
                float2 o = make_float2(acc[mb][nb][0] * m0, acc[mb][nb][1] * m0);
                *(float2*)(C + (size_t)r * NDIM + c) = o;
            }
            if (r + 8 < M) {
                float2 o = make_float2(acc[mb][nb][2] * m1, acc[mb][nb][3] * m1);
                *(float2*)(C + (size_t)(r + 8) * NDIM + c) = o;
            }
        }
    }
}

// ---------------- launch ----------------
extern "C" void kernel_launch(void* const* d_in, const int* in_sizes, int n_in,
                              void* d_out, int out_size) {
    const float* x  = (const float*)d_in[0];   // [N, 512]
    const int*   ei = (const int*)d_in[1];     // [2, E] int32
    const float* W  = (const float*)d_in[3];   // [512, 256]
    float* out = (float*)d_out;                // [N, 256]

    const int E = in_sizes[1] / 2;
    const int M = in_sizes[0] / KDIM;
    const int* dst = ei + E;
    const int e4 = E / 4;

    cudaFuncSetAttribute(k_gemm, cudaFuncAttributeMaxDynamicSharedMemorySize, SMEM_TOTAL);

    k_prep_w<<<(NDIM * KDIM + 255) / 256, 256>>>(W);
    k_zero_mask<<<(M + 255) / 256, 256>>>(M);
    k_scatter_mask<<<(e4 + 255) / 256, 256>>>(dst, e4, E);

    dim3 grid((M + BM - 1) / BM, NDIM / BN);
    k_gemm<<<grid, 256, SMEM_TOTAL>>>(x, out, M);
}

// round 5
// speedup vs baseline: 3.5765x; 1.4846x over previous
#include <cuda_runtime.h>
#include <cuda_fp16.h>
#include <cstdint>

#define KDIM 512
#define NDIM 256
#define BM 128
#define BN 128
#define KC 32
#define NSTAGE (KDIM / KC)   // 16

// Stage smem (bytes): A 8K | B 8K = 16K, double buffered = 32K
#define ST_A 0
#define ST_B 8192
#define STAGE_SZ 16384
#define SMEM_TOTAL (2 * STAGE_SZ)

__device__ unsigned char g_mask[65536];
__device__ __half g_Wh[NDIM * KDIM];   // [n][k] = fp16(W[k][n])

// ---------------- helpers ----------------
__device__ __forceinline__ uint32_t smem_u32(const void* p) {
    uint32_t a;
    asm("{ .reg .u64 t; cvta.to.shared.u64 t, %1; cvt.u32.u64 %0, t; }" : "=r"(a) : "l"(p));
    return a;
}
// rows of 64B (4 x 16B chunks); chunk permuted by row -> conflict-free ldmatrix/STS
__device__ __forceinline__ uint32_t swz(uint32_t row, uint32_t chunk) {
    return row * 64u + ((chunk ^ ((row & 6u) >> 1)) << 4);
}
__device__ __forceinline__ void ldm4(uint32_t* r, uint32_t addr) {
    asm volatile("ldmatrix.sync.aligned.m8n8.x4.shared.b16 {%0,%1,%2,%3}, [%4];"
                 : "=r"(r[0]), "=r"(r[1]), "=r"(r[2]), "=r"(r[3]) : "r"(addr));
}
__device__ __forceinline__ void mma16816(float* d, const uint32_t* a, uint32_t b0, uint32_t b1) {
    asm volatile("mma.sync.aligned.m16n8k16.row.col.f32.f16.f16.f32 "
                 "{%0,%1,%2,%3}, {%4,%5,%6,%7}, {%8,%9}, {%0,%1,%2,%3};"
                 : "+f"(d[0]), "+f"(d[1]), "+f"(d[2]), "+f"(d[3])
                 : "r"(a[0]), "r"(a[1]), "r"(a[2]), "r"(a[3]), "r"(b0), "r"(b1));
}
__device__ __forceinline__ void cpa16(uint32_t dst, const void* src) {
    asm volatile("cp.async.cg.shared.global [%0], [%1], 16;" :: "r"(dst), "l"(src));
}
__device__ __forceinline__ uint32_t pack_h2(__half a, __half b) {
    __half2 t = __halves2half2(a, b);
    return *(uint32_t*)&t;
}

// ---------------- prep kernels ----------------
// blocks [0,512): transpose+convert W; blocks [512,...): zero mask
__global__ void k_prep(const float* __restrict__ W, int n_nodes) {
    int b = blockIdx.x;
    if (b < (NDIM * KDIM) / 256) {
        int i = b * 256 + threadIdx.x;
        int k = i >> 8;
        int n = i & 255;
        g_Wh[(size_t)n * KDIM + k] = __float2half_rn(W[i]);   // W[k][n]
    } else {
        int i = (b - (NDIM * KDIM) / 256) * 256 + threadIdx.x;
        if (i < n_nodes) g_mask[i] = 0;
    }
}
__global__ void k_scatter_mask(const int* __restrict__ dst, int e4, int e) {
    int i = blockIdx.x * blockDim.x + threadIdx.x;
    if (i < e4) {
        int4 v = *(const int4*)(dst + 4 * i);
        g_mask[v.x] = 1; g_mask[v.y] = 1; g_mask[v.z] = 1; g_mask[v.w] = 1;
    }
    int r = e4 * 4 + i;
    if (r < e) g_mask[dst[r]] = 1;
}

// ---------------- GEMM: C = mask * (fp16(A) @ fp16(W)), HMMA ----------------
__global__ __launch_bounds__(256, 2)
void k_gemm(const float* __restrict__ A, float* __restrict__ C, int M)
{
    extern __shared__ char smem[];
    const uint32_t sbase = smem_u32(smem);
    const int tid  = threadIdx.x;
    const int lane = tid & 31;
    const int wid  = tid >> 5;
    const int warp_m = wid & 3;    // 0..3 -> 32 rows each
    const int warp_n = wid >> 2;   // 0..1 -> 64 cols each
    const int row0 = blockIdx.x * BM;
    const int n0   = blockIdx.y * BN;

    // A loader: 128 rows x 32 f32 -> thread = (row tid>>1, half tid&1) 16 floats
    const int arow  = tid >> 1;
    const int ahalf = tid & 1;
    const bool arow_ok = (row0 + arow) < M;
    const float* aptr = A + (size_t)(row0 + arow) * KDIM + ahalf * 16;
    const uint32_t a_sw0 = swz((uint32_t)arow, (uint32_t)(ahalf * 2 + 0));
    const uint32_t a_sw1 = swz((uint32_t)arow, (uint32_t)(ahalf * 2 + 1));
    // B loader: 128 rows x 32 f16 -> thread = (row tid>>1, half tid&1) 16 halves
    const __half* bptr = g_Wh + (size_t)(n0 + arow) * KDIM + ahalf * 16;

    float acc[2][8][4];
#pragma unroll
    for (int i = 0; i < 2; i++)
#pragma unroll
        for (int j = 0; j < 8; j++)
#pragma unroll
            for (int q = 0; q < 4; q++) acc[i][j][q] = 0.f;

    float4 av[4];   // 16 prefetched fp32

    auto sts_a = [&](char* buf) {
        uint4 c0, c1;
        c0.x = pack_h2(__float2half_rn(av[0].x), __float2half_rn(av[0].y));
        c0.y = pack_h2(__float2half_rn(av[0].z), __float2half_rn(av[0].w));
        c0.z = pack_h2(__float2half_rn(av[1].x), __float2half_rn(av[1].y));
        c0.w = pack_h2(__float2half_rn(av[1].z), __float2half_rn(av[1].w));
        c1.x = pack_h2(__float2half_rn(av[2].x), __float2half_rn(av[2].y));
        c1.y = pack_h2(__float2half_rn(av[2].z), __float2half_rn(av[2].w));
        c1.z = pack_h2(__float2half_rn(av[3].x), __float2half_rn(av[3].y));
        c1.w = pack_h2(__float2half_rn(av[3].z), __float2half_rn(av[3].w));
        *(uint4*)(buf + ST_A + a_sw0) = c0;
        *(uint4*)(buf + ST_A + a_sw1) = c1;
    };

    // ---- prologue: stage 0 -> buffer 0 ----
#pragma unroll
    for (int j = 0; j < 4; j++)
        av[j] = arow_ok ? *(const float4*)(aptr + 4 * j) : make_float4(0.f, 0.f, 0.f, 0.f);
    cpa16(sbase + ST_B + a_sw0, bptr);
    cpa16(sbase + ST_B + a_sw1, bptr + 8);
    asm volatile("cp.async.commit_group;" ::: "memory");
    sts_a(smem);
    asm volatile("cp.async.wait_group 0;" ::: "memory");
    __syncthreads();

    const uint32_t amrow = (uint32_t)(warp_m * 32 + (lane & 15));
    const uint32_t bnrow = (uint32_t)(warp_n * 64 + (lane & 15));
    const uint32_t chalf = (uint32_t)(lane >> 4);

    for (int t = 0; t < NSTAGE; t++) {
        const uint32_t buf = sbase + (uint32_t)(t & 1) * STAGE_SZ;

        if (t + 1 < NSTAGE) {
            const int koff = (t + 1) * KC;
#pragma unroll
            for (int j = 0; j < 4; j++)
                av[j] = arow_ok ? *(const float4*)(aptr + koff + 4 * j)
                                : make_float4(0.f, 0.f, 0.f, 0.f);
            const uint32_t nbuf = sbase + (uint32_t)((t + 1) & 1) * STAGE_SZ;
            cpa16(nbuf + ST_B + a_sw0, bptr + koff);
            cpa16(nbuf + ST_B + a_sw1, bptr + koff + 8);
            asm volatile("cp.async.commit_group;" ::: "memory");
        }

        // ---- compute stage t: 2 x k16 ----
#pragma unroll
        for (int ks = 0; ks < 2; ks++) {
            const uint32_t chunk = (uint32_t)ks * 2 + chalf;
            uint32_t ah[2][4], bh[4][4];
#pragma unroll
            for (int mb = 0; mb < 2; mb++)
                ldm4(ah[mb], buf + ST_A + swz(amrow + mb * 16, chunk));
#pragma unroll
            for (int j = 0; j < 4; j++)
                ldm4(bh[j], buf + ST_B + swz(bnrow + j * 16, chunk));
#pragma unroll
            for (int mb = 0; mb < 2; mb++)
#pragma unroll
                for (int j = 0; j < 4; j++) {
                    mma16816(acc[mb][2 * j + 0], ah[mb], bh[j][0], bh[j][2]);
                    mma16816(acc[mb][2 * j + 1], ah[mb], bh[j][1], bh[j][3]);
                }
        }

        if (t + 1 < NSTAGE) {
            sts_a(smem + ((t + 1) & 1) * STAGE_SZ);
            asm volatile("cp.async.wait_group 0;" ::: "memory");
            __syncthreads();
        }
    }

    // ---- epilogue: mask + store ----
    const int g  = lane >> 2;
    const int tg = lane & 3;
#pragma unroll
    for (int mb = 0; mb < 2; mb++) {
        int r = row0 + warp_m * 32 + mb * 16 + g;
        float m0 = (r     < M) ? (float)g_mask[r]     : 0.f;
        float m1 = (r + 8 < M) ? (float)g_mask[r + 8] : 0.f;
#pragma unroll
        for (int nb = 0; nb < 8; nb++) {
            int c = n0 + warp_n * 64 + nb * 8 + tg * 2;
            if (r < M) {
                float2 o = make_float2(acc[mb][nb][0] * m0, acc[mb][nb][1] * m0);
                *(float2*)(C + (size_t)r * NDIM + c) = o;
            }
            if (r + 8 < M) {
                float2 o = make_float2(acc[mb][nb][2] * m1, acc[mb][nb][3] * m1);
                *(float2*)(C + (size_t)(r + 8) * NDIM + c) = o;
            }
        }
    }
}

// ---------------- launch ----------------
extern "C" void kernel_launch(void* const* d_in, const int* in_sizes, int n_in,
                              void* d_out, int out_size) {
    const float* x  = (const float*)d_in[0];   // [N, 512]
    const int*   ei = (const int*)d_in[1];     // [2, E] int32
    const float* W  = (const float*)d_in[3];   // [512, 256]
    float* out = (float*)d_out;                // [N, 256]

    const int E = in_sizes[1] / 2;
    const int M = in_sizes[0] / KDIM;
    const int* dst = ei + E;
    const int e4 = E / 4;

    cudaFuncSetAttribute(k_gemm, cudaFuncAttributeMaxDynamicSharedMemorySize, SMEM_TOTAL);

    const int wblocks = (NDIM * KDIM) / 256;           // 512
    const int mblocks = (M + 255) / 256;
    k_prep<<<wblocks + mblocks, 256>>>(W, M);
    k_scatter_mask<<<(e4 + 255) / 256, 256>>>(dst, e4, E);

    dim3 grid((M + BM - 1) / BM, NDIM / BN);
    k_gemm<<<grid, 256, SMEM_TOTAL>>>(x, out, M);
}